// round 4
// baseline (speedup 1.0000x reference)
#include <cuda_runtime.h>
#include <cstdint>

// x: (B=8, H=256, W=256, C=64) fp32, WIN=16, half=8
// out: (B, 961, 16*16*64) fp32, partition order (0,0),(0,8),(8,0),(8,8)
// windows per partition: 256, 240, 240, 225 -> 961 per batch
//
// TMA bulk-copy formulation: each window = 16 contiguous 4KB input rows and
// ONE contiguous 64KB output region. Per block: 16x cp.async.bulk g->s into
// smem (mbarrier complete_tx), then one 64KB cp.async.bulk s->g. The TMA
// engine emits fully sequential 64KB write bursts -> better HBM row locality
// than per-warp STG.128. 64KB smem/CTA -> 3 CTAs/SM provide phase overlap.

#define NPB 961
#define IMG_ROW_BYTES (256 * 64 * 4)   // 65536 B per input image row
#define WROW_BYTES    (16 * 64 * 4)    // 4096 B per window row
#define WIN_BYTES     (16 * WROW_BYTES) // 65536 B per window
#define SMEM_BUF_OFF  128
#define SMEM_TOTAL    (SMEM_BUF_OFF + WIN_BYTES)

__global__ void __launch_bounds__(32)
partition_tma_kernel(const char* __restrict__ x, char* __restrict__ out)
{
    extern __shared__ char smem[];
    const uint32_t smem_base = (uint32_t)__cvta_generic_to_shared(smem);
    const uint32_t mbar = smem_base;                 // 8B mbarrier at offset 0
    const uint32_t buf  = smem_base + SMEM_BUF_OFF;  // 64KB window buffer

    const int blk = blockIdx.x;            // b * 961 + p
    const int b   = blk / NPB;
    const int p   = blk - b * NPB;

    int r0, c0, nc, base;
    if (p < 256)      { r0 = 0; c0 = 0; nc = 16; base = 0;   }
    else if (p < 496) { r0 = 0; c0 = 8; nc = 15; base = 256; }
    else if (p < 736) { r0 = 8; c0 = 0; nc = 16; base = 496; }
    else              { r0 = 8; c0 = 8; nc = 15; base = 736; }

    const int q  = p - base;
    const int wr = q / nc;
    const int wc = q - wr * nc;
    const int row0 = r0 + wr * 16;
    const int col0 = c0 + wc * 16;

    const char* src = x
        + (size_t)(b * 256 + row0) * IMG_ROW_BYTES
        + (size_t)col0 * (64 * 4);
    char* dst = out + (size_t)blk * WIN_BYTES;

    if (threadIdx.x == 0) {
        asm volatile("mbarrier.init.shared.b64 [%0], 1;" :: "r"(mbar) : "memory");
        asm volatile("fence.proxy.async.shared::cta;" ::: "memory");

        // Expect the full 64KB, then issue 16 bulk row loads.
        asm volatile("mbarrier.arrive.expect_tx.shared.b64 _, [%0], %1;"
                     :: "r"(mbar), "r"((uint32_t)WIN_BYTES) : "memory");
#pragma unroll
        for (int i = 0; i < 16; ++i) {
            asm volatile(
                "cp.async.bulk.shared::cta.global.mbarrier::complete_tx::bytes "
                "[%0], [%1], %2, [%3];"
                :: "r"(buf + i * WROW_BYTES),
                   "l"(src + (size_t)i * IMG_ROW_BYTES),
                   "r"((uint32_t)WROW_BYTES),
                   "r"(mbar)
                : "memory");
        }

        // Wait for all 16 rows (phase 0).
        {
            uint32_t done;
            asm volatile(
                "{\n\t.reg .pred P;\n\t"
                "WAITLOOP:\n\t"
                "mbarrier.try_wait.parity.shared.b64 P, [%1], 0, 0x989680;\n\t"
                "selp.b32 %0, 1, 0, P;\n\t"
                "@!P bra WAITLOOP;\n\t}"
                : "=r"(done) : "r"(mbar) : "memory");
        }
        asm volatile("fence.proxy.async.shared::cta;" ::: "memory");

        // Single 64KB sequential bulk store.
        asm volatile(
            "cp.async.bulk.global.shared::cta.bulk_group [%0], [%1], %2;"
            :: "l"(dst), "r"(buf), "r"((uint32_t)WIN_BYTES) : "memory");
        asm volatile("cp.async.bulk.commit_group;" ::: "memory");
        asm volatile("cp.async.bulk.wait_group.read 0;" ::: "memory");
    }
    __syncthreads();   // smem must stay live until the bulk store's reads finish
}

extern "C" void kernel_launch(void* const* d_in, const int* in_sizes, int n_in,
                              void* d_out, int out_size)
{
    const char* x = (const char*)d_in[0];
    char* out = (char*)d_out;
    cudaFuncSetAttribute(partition_tma_kernel,
                         cudaFuncAttributeMaxDynamicSharedMemorySize, SMEM_TOTAL);
    partition_tma_kernel<<<8 * NPB, 32, SMEM_TOTAL>>>(x, out);
}

// round 5
// speedup vs baseline: 1.0102x; 1.0102x over previous
#include <cuda_runtime.h>
#include <cstdint>

// x: (B=8, H=256, W=256, C=64) fp32, WIN=16, half=8
// out: (B, 961, 16*16*64) fp32, partition order (0,0),(0,8),(8,0),(8,8)
// windows per partition: 256, 240, 240, 225 -> 961 per batch
//
// Read path: 256 threads x 16 cp.async.cg (16B) -> smem. Full 64KB window in
// flight per CTA with ~24 regs (register-free MLP=16/thread).
// Write path: one 64KB cp.async.bulk smem->global (TMA) per window.
// 64KB smem/CTA -> 3 CTAs/SM; resident CTAs phase-stagger load vs store.

#define NPB 961
#define ROW_F4 (256 * 64 / 4)        // float4 per input image row = 4096
#define WIN_BYTES (16 * 16 * 64 * 4) // 65536 B per window

__global__ void __launch_bounds__(256, 3)
partition_kernel(const float4* __restrict__ x, char* __restrict__ out)
{
    __shared__ __align__(128) char buf[WIN_BYTES];
    const uint32_t sbuf = (uint32_t)__cvta_generic_to_shared(buf);

    const int blk = blockIdx.x;            // b * 961 + p
    const int b   = blk / NPB;
    const int p   = blk - b * NPB;

    int r0, c0, nc, base;
    if (p < 256)      { r0 = 0; c0 = 0; nc = 16; base = 0;   }
    else if (p < 496) { r0 = 0; c0 = 8; nc = 15; base = 256; }
    else if (p < 736) { r0 = 8; c0 = 0; nc = 16; base = 496; }
    else              { r0 = 8; c0 = 8; nc = 15; base = 736; }

    const int q  = p - base;
    const int wr = q / nc;
    const int wc = q - wr * nc;
    const int row0 = r0 + wr * 16;
    const int col0 = c0 + wc * 16;

    const float4* __restrict__ src = x
        + (size_t)(b * 256 + row0) * ROW_F4 + (size_t)col0 * 16;
    char* dst = out + (size_t)blk * WIN_BYTES;

    const int t = threadIdx.x;             // 0..255: one float4 of each 4KB row

    // 16 independent 16B async copies per thread, zero data registers.
#pragma unroll
    for (int i = 0; i < 16; ++i) {
        const float4* g = src + (size_t)i * ROW_F4 + t;
        uint32_t s = sbuf + (uint32_t)((i * 256 + t) * 16);
        asm volatile("cp.async.cg.shared.global [%0], [%1], 16;"
                     :: "r"(s), "l"(g) : "memory");
    }
    asm volatile("cp.async.commit_group;" ::: "memory");
    asm volatile("cp.async.wait_group 0;" ::: "memory");
    __syncthreads();

    if (t == 0) {
        asm volatile("fence.proxy.async.shared::cta;" ::: "memory");
        asm volatile(
            "cp.async.bulk.global.shared::cta.bulk_group [%0], [%1], %2;"
            :: "l"(dst), "r"(sbuf), "r"((uint32_t)WIN_BYTES) : "memory");
        asm volatile("cp.async.bulk.commit_group;" ::: "memory");
        asm volatile("cp.async.bulk.wait_group.read 0;" ::: "memory");
    }
    __syncthreads();   // keep smem live until the bulk store's reads complete
}

extern "C" void kernel_launch(void* const* d_in, const int* in_sizes, int n_in,
                              void* d_out, int out_size)
{
    const float4* x = (const float4*)d_in[0];
    char* out = (char*)d_out;
    partition_kernel<<<8 * NPB, 256>>>(x, out);
}